// round 9
// baseline (speedup 1.0000x reference)
#include <cuda_runtime.h>

#define NB 262144
#define NTHREADS (NB / 2)   // 2 elements per thread
#define BLOCK 128

typedef unsigned long long u64;

__device__ __forceinline__ u64 pack2(float lo, float hi) {
    u64 r; asm("mov.b64 %0, {%1,%2};" : "=l"(r) : "f"(lo), "f"(hi)); return r;
}
__device__ __forceinline__ void unpack2(u64 v, float& lo, float& hi) {
    asm("mov.b64 {%0,%1}, %2;" : "=f"(lo), "=f"(hi) : "l"(v));
}
__device__ __forceinline__ u64 fma2(u64 a, u64 b, u64 c) {
    u64 r; asm("fma.rn.f32x2 %0, %1, %2, %3;" : "=l"(r) : "l"(a), "l"(b), "l"(c)); return r;
}
__device__ __forceinline__ u64 mul2(u64 a, u64 b) {
    u64 r; asm("mul.rn.f32x2 %0, %1, %2;" : "=l"(r) : "l"(a), "l"(b)); return r;
}
__device__ __forceinline__ u64 relu2(u64 x) {
    float lo, hi; unpack2(x, lo, hi);
    lo = fmaxf(lo, 0.0f); hi = fmaxf(hi, 0.0f);
    return pack2(lo, hi);
}

__global__ __launch_bounds__(BLOCK, 6)
void hybridq_kernel(const float* __restrict__ xq, const float* __restrict__ xc,
                    const float* __restrict__ qp,
                    const float* __restrict__ W1, const float* __restrict__ b1,
                    const float* __restrict__ W2, const float* __restrict__ b2,
                    const float* __restrict__ W3, const float* __restrict__ b3,
                    float* __restrict__ out)
{
    // Feature-pair-packed weights: each u64 holds TWO DISTINCT weights.
    // One SMEM row per k: [W1 pairs x8 | (W1q,b1) | W2 pairs x8] = 17 u64 -> pad 18.
    __shared__ u64 sWk[32][18];
    __shared__ u64 sW3[8];       // W3 native pairs
    __shared__ u64 sb2[8];       // b2 native pairs

    const int tid = threadIdx.x;
    for (int i = tid; i < 32 * 8; i += BLOCK) {
        int k = i / 8, j = i % 8;
        sWk[k][j] = pack2(W1[(1 + 2 * j) * 32 + k], W1[(2 + 2 * j) * 32 + k]);
        sWk[k][9 + j] = ((const u64*)W2)[k * 8 + j];
    }
    if (tid < 32) sWk[tid][8] = pack2(W1[tid], b1[tid]);   // (W1[0][k], b1[k])
    if (tid < 8) {
        sW3[tid] = ((const u64*)W3)[tid];
        sb2[tid] = ((const u64*)b2)[tid];
    }
    __syncthreads();

    const int t = blockIdx.x * BLOCK + tid;

    // ---- Quantum feature: <Z0> = prod_{i=1..6} cos(x_q[i] + qp[i]) ----
    // (CNOT-ring GF(2): qubit-0 output = parity(b1..b6); per-qubit factor
    //  cos^2(h)-sin^2(h) = cos(2h) = cos(x+w); qubit 0's own angle cancels.)
    float q0 = 1.0f, q1 = 1.0f;
#pragma unroll
    for (int i = 1; i < 7; i++) {
        float w = __ldg(qp + i);
        q0 *= __cosf(__ldg(xq + (size_t)t * 7 + i) + w);
        q1 *= __cosf(__ldg(xq + ((size_t)t + NTHREADS) * 7 + i) + w);
    }

    // ---- Inputs: 8 native xc pairs + (q, 1) pair (bias folded as feature) ----
    u64 in[2][9];
    in[0][8] = pack2(q0, 1.0f);
    in[1][8] = pack2(q1, 1.0f);
    {
        const ulonglong2* c0 = (const ulonglong2*)(xc + (size_t)t * 16);
        const ulonglong2* c1 = (const ulonglong2*)(xc + ((size_t)t + NTHREADS) * 16);
#pragma unroll
        for (int p = 0; p < 4; p++) {
            ulonglong2 a = c0[p]; in[0][2 * p] = a.x; in[0][2 * p + 1] = a.y;
            ulonglong2 b = c1[p]; in[1][2 * p] = b.x; in[1][2 * p + 1] = b.y;
        }
    }

    // ---- h2 accumulators: 8 output-pairs per element, init with b2 ----
    u64 h2[2][8];
#pragma unroll
    for (int e = 0; e < 2; e++)
#pragma unroll
        for (int j = 0; j < 8; j++)
            h2[e][j] = sb2[j];

    // ---- Fused layers 1+2 ----
#pragma unroll 1
    for (int k = 0; k < 32; k++) {
        const ulonglong2* row = (const ulonglong2*)&sWk[k][0];
        ulonglong2 w01 = row[0];
        ulonglong2 w23 = row[1];
        ulonglong2 w45 = row[2];
        ulonglong2 w67 = row[3];
        u64 wqb = sWk[k][8];

        u64 a2[2];
#pragma unroll
        for (int e = 0; e < 2; e++) {
            u64 acc = mul2(in[e][0], w01.x);
            acc = fma2(in[e][1], w01.y, acc);
            acc = fma2(in[e][2], w23.x, acc);
            acc = fma2(in[e][3], w23.y, acc);
            acc = fma2(in[e][4], w45.x, acc);
            acc = fma2(in[e][5], w45.y, acc);
            acc = fma2(in[e][6], w67.x, acc);
            acc = fma2(in[e][7], w67.y, acc);
            acc = fma2(in[e][8], wqb, acc);   // q*W1q + bias in the two halves
            float lo, hi;
            unpack2(acc, lo, hi);             // free: register pair
            float s = fmaxf(lo + hi, 0.0f);
            a2[e] = pack2(s, s);
        }

        ulonglong2 v01 = row[4];   // sWk[k][9..16] not 16B-aligned? row[4] = u64 idx 8,9
        // careful: row[] indexes 16B units; sWk[k][9] starts mid-pair.
        // Load W2 pairs individually (LDS.64 broadcast, same wavefront cost).
        const u64* w2r = &sWk[k][9];
        u64 v0 = w2r[0], v1 = w2r[1], v2 = w2r[2], v3 = w2r[3];
        u64 v4 = w2r[4], v5 = w2r[5], v6 = w2r[6], v7 = w2r[7];
        (void)v01;
#pragma unroll
        for (int e = 0; e < 2; e++) {
            h2[e][0] = fma2(a2[e], v0, h2[e][0]);
            h2[e][1] = fma2(a2[e], v1, h2[e][1]);
            h2[e][2] = fma2(a2[e], v2, h2[e][2]);
            h2[e][3] = fma2(a2[e], v3, h2[e][3]);
            h2[e][4] = fma2(a2[e], v4, h2[e][4]);
            h2[e][5] = fma2(a2[e], v5, h2[e][5]);
            h2[e][6] = fma2(a2[e], v6, h2[e][6]);
            h2[e][7] = fma2(a2[e], v7, h2[e][7]);
        }
    }

    // ---- Layer 3: relu(h2) . W3 + b3, pairwise then hsum ----
    float bb = __ldg(b3);
#pragma unroll
    for (int e = 0; e < 2; e++) {
        u64 acc = mul2(relu2(h2[e][0]), sW3[0]);
#pragma unroll
        for (int j = 1; j < 8; j++)
            acc = fma2(relu2(h2[e][j]), sW3[j], acc);
        float lo, hi;
        unpack2(acc, lo, hi);
        out[t + e * NTHREADS] = bb + lo + hi;
    }
}

extern "C" void kernel_launch(void* const* d_in, const int* in_sizes, int n_in,
                              void* d_out, int out_size)
{
    const float* xq = (const float*)d_in[0];
    const float* xc = (const float*)d_in[1];
    const float* qp = (const float*)d_in[2];
    const float* W1 = (const float*)d_in[3];
    const float* b1 = (const float*)d_in[4];
    const float* W2 = (const float*)d_in[5];
    const float* b2 = (const float*)d_in[6];
    const float* W3 = (const float*)d_in[7];
    const float* b3 = (const float*)d_in[8];
    float* out = (float*)d_out;

    hybridq_kernel<<<NTHREADS / BLOCK, BLOCK>>>(xq, xc, qp, W1, b1, W2, b2, W3, b3, out);
}